// round 2
// baseline (speedup 1.0000x reference)
#include <cuda_runtime.h>
#include <cstdint>

#define N_NODES 100000
#define N_EDGES 1600000
#define D 128

// Scratch: h = x @ W  (51.2 MB, static device array — no allocations allowed)
__device__ float g_h[(size_t)N_NODES * D];

// ---------------------------------------------------------------------------
// Kernel 1: out[n][c] = bias[c]  (also serves as zero-init for scatter-add)
// ---------------------------------------------------------------------------
__global__ void init_out_kernel(float* __restrict__ out, const float* __restrict__ bias) {
    __shared__ float4 bs[32];
    if (threadIdx.x < 32) bs[threadIdx.x] = ((const float4*)bias)[threadIdx.x];
    __syncthreads();
    size_t total = (size_t)N_NODES * 32;  // float4 elements
    float4* out4 = (float4*)out;
    for (size_t i = (size_t)blockIdx.x * blockDim.x + threadIdx.x; i < total;
         i += (size_t)gridDim.x * blockDim.x) {
        out4[i] = bs[i & 31];
    }
}

// ---------------------------------------------------------------------------
// Kernel 2: h = x @ W
// Block = 128 threads = 4 warps. Each warp computes ROWS_PER_WARP rows,
// each lane computes 4 output columns (float4). W (64 KB) stays L1-resident.
// ---------------------------------------------------------------------------
#define ROWS_PER_WARP 4
#define ROWS_PER_BLOCK (4 * ROWS_PER_WARP)  // 16; 100000/16 = 6250 blocks exact

__global__ __launch_bounds__(128) void gemm_kernel(const float* __restrict__ x,
                                                   const float* __restrict__ W) {
    __shared__ float xs[ROWS_PER_BLOCK][D];
    int tid  = threadIdx.x;
    int warp = tid >> 5;
    int lane = tid & 31;
    int row0 = blockIdx.x * ROWS_PER_BLOCK;

    // cooperative vectorized load of 16 x-rows into smem
    const float4* xsrc = (const float4*)(x + (size_t)row0 * D);
    float4* xdst = (float4*)&xs[0][0];
    #pragma unroll
    for (int i = 0; i < ROWS_PER_BLOCK * D / 4 / 128; i++) {
        xdst[tid + i * 128] = xsrc[tid + i * 128];
    }
    __syncthreads();

    const float4* W4 = (const float4*)W;  // viewed as [D][32] float4
    for (int r = 0; r < ROWS_PER_WARP; r++) {
        int lr = warp * ROWS_PER_WARP + r;
        float4 acc = make_float4(0.f, 0.f, 0.f, 0.f);
        #pragma unroll
        for (int k = 0; k < D; k++) {
            float xv = xs[lr][k];
            float4 w = __ldg(&W4[k * 32 + lane]);
            acc.x += xv * w.x;
            acc.y += xv * w.y;
            acc.z += xv * w.z;
            acc.w += xv * w.w;
        }
        ((float4*)(g_h + (size_t)(row0 + lr) * D))[lane] = acc;
    }
}

// ---------------------------------------------------------------------------
// Kernel 3: per-edge message + scatter-add.
// One warp per edge; each lane handles 4 contiguous floats (float4).
// Scatter uses red.global.add.v4.f32 (16B vector reduction, sm_90+).
// NOTE: edge_index arrives as int32 (JAX default x64-disabled downcasts int64).
// ---------------------------------------------------------------------------
__global__ __launch_bounds__(256) void edge_kernel(const int* __restrict__ ei,
                                                   const float* __restrict__ ea,
                                                   float* __restrict__ out) {
    int e = blockIdx.x * (blockDim.x >> 5) + (threadIdx.x >> 5);
    if (e >= N_EDGES) return;
    int lane = threadIdx.x & 31;

    int src = __ldg(&ei[e]);
    int dst = __ldg(&ei[N_EDGES + e]);

    float4 h = ((const float4*)(g_h + (size_t)src * D))[lane];
    float4 a = __ldg(&((const float4*)(ea + (size_t)e * D))[lane]);

    float4 m;
    m.x = fmaxf(h.x + a.x, 0.f);
    m.y = fmaxf(h.y + a.y, 0.f);
    m.z = fmaxf(h.z + a.z, 0.f);
    m.w = fmaxf(h.w + a.w, 0.f);

    float* addr = out + (size_t)dst * D + lane * 4;
    asm volatile("red.global.add.v4.f32 [%0], {%1,%2,%3,%4};"
                 :: "l"(addr), "f"(m.x), "f"(m.y), "f"(m.z), "f"(m.w)
                 : "memory");
}

// ---------------------------------------------------------------------------
extern "C" void kernel_launch(void* const* d_in, const int* in_sizes, int n_in,
                              void* d_out, int out_size) {
    const float* x    = (const float*)d_in[0];
    const int*   ei   = (const int*)d_in[1];
    const float* ea   = (const float*)d_in[2];
    const float* W    = (const float*)d_in[3];
    const float* bias = (const float*)d_in[4];
    float*       out  = (float*)d_out;

    // 1) out = bias (broadcast) — also the zero base for scatter-add
    init_out_kernel<<<592, 256>>>(out, bias);

    // 2) h = x @ W
    gemm_kernel<<<N_NODES / ROWS_PER_BLOCK, 128>>>(x, W);

    // 3) scatter relu(h[src] + edge_attr) into out[dst]
    int warps_per_block = 256 / 32;  // 8 edges per block
    int blocks = (N_EDGES + warps_per_block - 1) / warps_per_block;
    edge_kernel<<<blocks, 256>>>(ei, ea, out);
}